// round 5
// baseline (speedup 1.0000x reference)
#include <cuda_runtime.h>
#include <cuda_bf16.h>
#include <cuda_fp16.h>
#include <mma.h>
#include <math_constants.h>

using namespace nvcuda;

// Problem constants
#define N_NODES   50000
#define N_EDGES   800000
#define IN_FEATS  256
#define EDGE_FEATS 64
#define NUM_HEADS 4
#define OUT_FEATS 32
#define HF        128           // NUM_HEADS*OUT_FEATS
#define QCOLS     256           // NUM_HEADS*EDGE_FEATS

#define SCAN_BLK  512
#define NB_SCAN   ((N_NODES + SCAN_BLK - 1) / SCAN_BLK)   // 98

// Scratch (static device globals; no allocation allowed)
__device__ __half g_af16[N_NODES * IN_FEATS];  // node_feat fp16
__device__ __half g_wf16[IN_FEATS * HF];       // W_node fp16
__device__ float  g_h[N_NODES * HF];           // projected node feats fp32
__device__ __half g_hh[N_NODES * HF];          // projected node feats fp16 (for gather)
__device__ __half g_qh[N_NODES * QCOLS];       // q[n,h,k] fp16, pre-scaled by 1/sqrt(32)
__device__ int    g_cnt[N_NODES];
__device__ int    g_off[N_NODES + 1];
__device__ int    g_cur[N_NODES];
__device__ int    g_eid[N_EDGES];
__device__ int    g_psrc[N_EDGES];
__device__ int    g_part[NB_SCAN];
__device__ int    g_partx[NB_SCAN];

// ---------------------------------------------------------------------------
__global__ void zero_cnt_kernel() {
    int i = blockIdx.x * blockDim.x + threadIdx.x;
    if (i < N_NODES) g_cnt[i] = 0;
}

// ---------------------------------------------------------------------------
// convert inputs to fp16 (vectorized: float4 -> 4 halves)
// ---------------------------------------------------------------------------
__global__ void tohalf_kernel(const float* __restrict__ A, const float* __restrict__ W) {
    int i = blockIdx.x * blockDim.x + threadIdx.x;
    int stride = gridDim.x * blockDim.x;
    const int nA4 = (N_NODES * IN_FEATS) / 4;
    for (int j = i; j < nA4; j += stride) {
        float4 v = ((const float4*)A)[j];
        __half2 lo = __floats2half2_rn(v.x, v.y);
        __half2 hi = __floats2half2_rn(v.z, v.w);
        ((__half2*)g_af16)[j * 2]     = lo;
        ((__half2*)g_af16)[j * 2 + 1] = hi;
    }
    const int nW4 = (IN_FEATS * HF) / 4;
    for (int j = i; j < nW4; j += stride) {
        float4 v = ((const float4*)W)[j];
        __half2 lo = __floats2half2_rn(v.x, v.y);
        __half2 hi = __floats2half2_rn(v.z, v.w);
        ((__half2*)g_wf16)[j * 2]     = lo;
        ((__half2*)g_wf16)[j * 2 + 1] = hi;
    }
}

// ---------------------------------------------------------------------------
// K1: h = node_feat @ W_node via wmma (fp16 in, fp32 accum).
// Block = 256 threads = 8 warps; warp w -> N cols [16w,16w+16); block -> 16 M rows.
// ---------------------------------------------------------------------------
__global__ __launch_bounds__(256) void gemm_wmma_kernel() {
    const int warp = threadIdx.x >> 5;
    const int m0 = blockIdx.x * 16;
    const int n0 = warp * 16;

    wmma::fragment<wmma::accumulator, 16, 16, 16, float> c;
    wmma::fill_fragment(c, 0.0f);

#pragma unroll
    for (int k = 0; k < IN_FEATS; k += 16) {
        wmma::fragment<wmma::matrix_a, 16, 16, 16, __half, wmma::row_major> a;
        wmma::fragment<wmma::matrix_b, 16, 16, 16, __half, wmma::row_major> b;
        wmma::load_matrix_sync(a, g_af16 + (size_t)m0 * IN_FEATS + k, IN_FEATS);
        wmma::load_matrix_sync(b, g_wf16 + (size_t)k * HF + n0, HF);
        wmma::mma_sync(c, a, b, c);
    }
    wmma::store_matrix_sync(g_h + (size_t)m0 * HF + n0, c, HF, wmma::mem_row_major);
}

// ---------------------------------------------------------------------------
// h -> fp16 copy for fused gather
// ---------------------------------------------------------------------------
__global__ void h2half_kernel() {
    int i = blockIdx.x * blockDim.x + threadIdx.x;
    int stride = gridDim.x * blockDim.x;
    const int n4 = (N_NODES * HF) / 4;
    for (int j = i; j < n4; j += stride) {
        float4 v = ((const float4*)g_h)[j];
        ((__half2*)g_hh)[j * 2]     = __floats2half2_rn(v.x, v.y);
        ((__half2*)g_hh)[j * 2 + 1] = __floats2half2_rn(v.z, v.w);
    }
}

// ---------------------------------------------------------------------------
// K2: q[n,h,k] = (1/sqrt(32)) * sum_f h[n,h*32+f] * W_edge[k, h*32+f]
// Computed fp32 (from fp32 h), stored fp16.
// ---------------------------------------------------------------------------
__global__ __launch_bounds__(256) void make_q_kernel(const float* __restrict__ We) {
    __shared__ float WeT[HF * EDGE_FEATS];   // WeT[c*64 + k] = We[k*128 + c]
    __shared__ float hs[4][HF];

    const int tid = threadIdx.x;
    for (int i = tid; i < EDGE_FEATS * HF; i += 256) {
        int k = i >> 7, c = i & 127;
        WeT[c * EDGE_FEATS + k] = We[i];
    }

    const int hh = tid >> 6;
    const int k  = tid & 63;
    const int node0 = blockIdx.x * 16;
    const float scale = 0.17677669529663687f;   // 1/sqrt(32)

    for (int g = 0; g < 4; g++) {
        __syncthreads();
        for (int i = tid; i < 4 * HF; i += 256) {
            int ni = i >> 7, c = i & 127;
            int n = node0 + g * 4 + ni;
            hs[ni][c] = (n < N_NODES) ? g_h[n * HF + c] : 0.0f;
        }
        __syncthreads();

        float acc[4] = {0.f, 0.f, 0.f, 0.f};
#pragma unroll
        for (int f = 0; f < OUT_FEATS; f++) {
            float w = WeT[(hh * OUT_FEATS + f) * EDGE_FEATS + k];
#pragma unroll
            for (int ni = 0; ni < 4; ni++) acc[ni] += hs[ni][hh * OUT_FEATS + f] * w;
        }
#pragma unroll
        for (int ni = 0; ni < 4; ni++) {
            int n = node0 + g * 4 + ni;
            if (n < N_NODES)
                g_qh[(n * NUM_HEADS + hh) * EDGE_FEATS + k] = __float2half_rn(acc[ni] * scale);
        }
    }
}

// ---------------------------------------------------------------------------
// CSR build: histogram -> scan (3 kernels) -> scatter (eid + psrc)
// ---------------------------------------------------------------------------
__global__ void hist_kernel(const int* __restrict__ dst) {
    int e = blockIdx.x * blockDim.x + threadIdx.x;
    if (e < N_EDGES) atomicAdd(&g_cnt[dst[e]], 1);
}

__global__ __launch_bounds__(SCAN_BLK) void scan1_kernel() {
    __shared__ int sm[SCAN_BLK];
    int t = threadIdx.x;
    int i = blockIdx.x * SCAN_BLK + t;
    sm[t] = (i < N_NODES) ? g_cnt[i] : 0;
    __syncthreads();
    for (int off = SCAN_BLK / 2; off > 0; off >>= 1) {
        if (t < off) sm[t] += sm[t + off];
        __syncthreads();
    }
    if (t == 0) g_part[blockIdx.x] = sm[0];
}

__global__ __launch_bounds__(128) void scan2_kernel() {
    __shared__ int sm[2][128];
    int t = threadIdx.x;
    int v = (t < NB_SCAN) ? g_part[t] : 0;
    int pi = 0;
    sm[0][t] = v;
    __syncthreads();
#pragma unroll
    for (int off = 1; off < 128; off <<= 1) {
        int add = (t >= off) ? sm[pi][t - off] : 0;
        sm[pi ^ 1][t] = sm[pi][t] + add;
        pi ^= 1;
        __syncthreads();
    }
    if (t < NB_SCAN) g_partx[t] = sm[pi][t] - v;   // exclusive
}

__global__ __launch_bounds__(SCAN_BLK) void scan3_kernel() {
    __shared__ int sm[2][SCAN_BLK];
    int t = threadIdx.x;
    int i = blockIdx.x * SCAN_BLK + t;
    int v = (i < N_NODES) ? g_cnt[i] : 0;
    int pi = 0;
    sm[0][t] = v;
    __syncthreads();
#pragma unroll
    for (int off = 1; off < SCAN_BLK; off <<= 1) {
        int add = (t >= off) ? sm[pi][t - off] : 0;
        sm[pi ^ 1][t] = sm[pi][t] + add;
        pi ^= 1;
        __syncthreads();
    }
    if (i < N_NODES) {
        int excl = g_partx[blockIdx.x] + sm[pi][t] - v;
        g_off[i] = excl;
        g_cur[i] = excl;
    }
    if (blockIdx.x == 0 && t == 0) g_off[N_NODES] = N_EDGES;
}

__global__ void scatter_kernel(const int* __restrict__ src, const int* __restrict__ dst) {
    int e = blockIdx.x * blockDim.x + threadIdx.x;
    if (e < N_EDGES) {
        int pos = atomicAdd(&g_cur[dst[e]], 1);
        g_eid[pos]  = e;
        g_psrc[pos] = src[e];
    }
}

// ---------------------------------------------------------------------------
// Fused: warp per dst node, NO max subtraction (softmax shift-invariant,
// scores O(1)). lane l: head h=l>>3, k-chunk k0=(l&7)*8.
// ---------------------------------------------------------------------------
__global__ __launch_bounds__(256) void fused_kernel(
    const float* __restrict__ ef, float* __restrict__ out) {
    const int d = (blockIdx.x * 256 + threadIdx.x) >> 5;
    if (d >= N_NODES) return;
    const int lane = threadIdx.x & 31;
    const int h  = lane >> 3;
    const int k0 = (lane & 7) * 8;

    const int beg = __ldg(&g_off[d]);
    const int end = __ldg(&g_off[d + 1]);

    float den = 0.0f;
    float4 acc = make_float4(0.f, 0.f, 0.f, 0.f);

    int eid = 0, s = 0;
    if (beg < end) {
        eid = __ldg(&g_eid[beg]);
        s   = __ldg(&g_psrc[beg]);
    }

    for (int j = beg; j < end; j++) {
        const int eid_c = eid;
        const int s_c = s;
        if (j + 1 < end) {
            eid = __ldg(&g_eid[j + 1]);
            s   = __ldg(&g_psrc[j + 1]);
        }

        const float4 ef0 = *(const float4*)(ef + (size_t)eid_c * EDGE_FEATS + k0);
        const float4 ef1 = *(const float4*)(ef + (size_t)eid_c * EDGE_FEATS + k0 + 4);

        const uint4 qv = *(const uint4*)(g_qh + (size_t)s_c * QCOLS + h * EDGE_FEATS + k0);
        const float2 q0 = __half22float2(*(const __half2*)&qv.x);
        const float2 q1 = __half22float2(*(((const __half2*)&qv.x) + 1));
        const float2 q2 = __half22float2(*(const __half2*)&qv.z);
        const float2 q3 = __half22float2(*(((const __half2*)&qv.z) + 1));

        float p = ef0.x * q0.x + ef0.y * q0.y + ef0.z * q1.x + ef0.w * q1.y
                + ef1.x * q2.x + ef1.y * q2.y + ef1.z * q3.x + ef1.w * q3.y;
        p += __shfl_xor_sync(0xffffffffu, p, 1);
        p += __shfl_xor_sync(0xffffffffu, p, 2);
        p += __shfl_xor_sync(0xffffffffu, p, 4);

        const float sc = (p > 0.0f) ? p : 0.01f * p;       // leaky relu
        const float w  = __expf(sc);

        // h gather fp16: 8B per lane (lane covers features [4l, 4l+4))
        const uint2 hvu = *(const uint2*)(g_hh + (size_t)s_c * HF + lane * 4);
        const float2 h01 = __half22float2(*(const __half2*)&hvu.x);
        const float2 h23 = __half22float2(*(const __half2*)&hvu.y);

        den   += w;
        acc.x += w * h01.x;
        acc.y += w * h01.y;
        acc.z += w * h23.x;
        acc.w += w * h23.y;
    }

    const float inv = (den > 0.0f) ? __frcp_rn(den) : 0.0f;
    float4 o = make_float4(acc.x * inv, acc.y * inv, acc.z * inv, acc.w * inv);
    *(float4*)(out + (size_t)d * HF + lane * 4) = o;
}

// ---------------------------------------------------------------------------
extern "C" void kernel_launch(void* const* d_in, const int* in_sizes, int n_in,
                              void* d_out, int out_size) {
    const float* node_feat = (const float*)d_in[0];
    const float* edge_feat = (const float*)d_in[1];
    const int*   src       = (const int*)d_in[2];
    const int*   dst       = (const int*)d_in[3];
    const float* W_node    = (const float*)d_in[4];
    const float* W_edge    = (const float*)d_in[5];
    float* out = (float*)d_out;

    zero_cnt_kernel<<<(N_NODES + 255) / 256, 256>>>();
    tohalf_kernel<<<2048, 256>>>(node_feat, W_node);
    gemm_wmma_kernel<<<N_NODES / 16, 256>>>();            // 3125 blocks
    h2half_kernel<<<2048, 256>>>();
    make_q_kernel<<<(N_NODES + 15) / 16, 256>>>(W_edge);
    hist_kernel<<<(N_EDGES + 255) / 256, 256>>>(dst);
    scan1_kernel<<<NB_SCAN, SCAN_BLK>>>();
    scan2_kernel<<<1, 128>>>();
    scan3_kernel<<<NB_SCAN, SCAN_BLK>>>();
    scatter_kernel<<<(N_EDGES + 255) / 256, 256>>>(src, dst);
    fused_kernel<<<(N_NODES * 32 + 255) / 256, 256>>>(edge_feat, out);
}

// round 6
// speedup vs baseline: 1.2524x; 1.2524x over previous
#include <cuda_runtime.h>
#include <cuda_bf16.h>
#include <cuda_fp16.h>
#include <mma.h>
#include <math_constants.h>

using namespace nvcuda;

// Problem constants
#define N_NODES   50000
#define N_PAD     50048         // padded rows so last GEMM block can store full tiles
#define N_EDGES   800000
#define IN_FEATS  256
#define EDGE_FEATS 64
#define NUM_HEADS 4
#define OUT_FEATS 32
#define HF        128           // NUM_HEADS*OUT_FEATS
#define QCOLS     256           // NUM_HEADS*EDGE_FEATS

#define SCAN_BLK  512
#define NB_SCAN   ((N_NODES + SCAN_BLK - 1) / SCAN_BLK)   // 98

#define GM_BM 128
#define GM_BK 32

// Scratch (static device globals; no allocation allowed)
__device__ float  g_h[N_PAD * HF];             // projected node feats fp32 (padded)
__device__ __half g_hh[N_NODES * HF];          // projected node feats fp16 (gather copy)
__device__ __half g_qh[N_NODES * QCOLS];       // q[n,h,k] fp16, pre-scaled by 1/sqrt(32)
__device__ int    g_cnt[N_NODES];
__device__ int    g_off[N_NODES + 1];
__device__ int    g_cur[N_NODES];
__device__ int    g_eid[N_EDGES];
__device__ int    g_psrc[N_EDGES];
__device__ int    g_part[NB_SCAN];
__device__ int    g_partx[NB_SCAN];

// ---------------------------------------------------------------------------
__global__ void zero_cnt_kernel() {
    int i = blockIdx.x * blockDim.x + threadIdx.x;
    if (i < N_NODES) g_cnt[i] = 0;
}

// ---------------------------------------------------------------------------
// K1: h = node_feat[N,256] @ W_node[256,128] via wmma, smem-staged.
// fp32 global loads converted to fp16 in the smem store (no separate pass).
// 8 warps: warp (wm,wn) owns 32x64 tile = 2x4 fragments, fp32 accum.
// ---------------------------------------------------------------------------
__global__ __launch_bounds__(256) void gemm_wmma_kernel(
    const float* __restrict__ A, const float* __restrict__ W) {
    __shared__ __half As[GM_BM][GM_BK + 8];   // ldm = 40 (80B, 16B-aligned rows)
    __shared__ __half Ws[GM_BK][HF + 8];      // ldm = 136 (272B)

    const int tid  = threadIdx.x;
    const int warp = tid >> 5;
    const int wm   = warp >> 1;     // 0..3
    const int wn   = warp & 1;      // 0..1
    const int m0   = blockIdx.x * GM_BM;

    wmma::fragment<wmma::accumulator, 16, 16, 16, float> c[2][4];
#pragma unroll
    for (int i = 0; i < 2; i++)
#pragma unroll
        for (int j = 0; j < 4; j++) wmma::fill_fragment(c[i][j], 0.0f);

    for (int k0 = 0; k0 < IN_FEATS; k0 += GM_BK) {
        // A tile: 128x32 fp32 = 1024 float4; 4 per thread; convert to half
#pragma unroll
        for (int i = 0; i < 4; i++) {
            int idx = tid + i * 256;        // 0..1023
            int row = idx >> 3;             // 8 float4 per row
            int col = (idx & 7) * 4;
            float4 v = make_float4(0.f, 0.f, 0.f, 0.f);
            int gr = m0 + row;
            if (gr < N_NODES) v = *(const float4*)&A[(size_t)gr * IN_FEATS + k0 + col];
            As[row][col + 0] = __float2half_rn(v.x);
            As[row][col + 1] = __float2half_rn(v.y);
            As[row][col + 2] = __float2half_rn(v.z);
            As[row][col + 3] = __float2half_rn(v.w);
        }
        // W tile: 32x128 fp32 = 1024 float4; 4 per thread
#pragma unroll
        for (int i = 0; i < 4; i++) {
            int idx = tid + i * 256;
            int row = idx >> 5;             // 32 float4 per row
            int col = (idx & 31) * 4;
            float4 v = *(const float4*)&W[(size_t)(k0 + row) * HF + col];
            Ws[row][col + 0] = __float2half_rn(v.x);
            Ws[row][col + 1] = __float2half_rn(v.y);
            Ws[row][col + 2] = __float2half_rn(v.z);
            Ws[row][col + 3] = __float2half_rn(v.w);
        }
        __syncthreads();

#pragma unroll
        for (int kk = 0; kk < GM_BK; kk += 16) {
            wmma::fragment<wmma::matrix_a, 16, 16, 16, __half, wmma::row_major> a[2];
            wmma::fragment<wmma::matrix_b, 16, 16, 16, __half, wmma::row_major> b[4];
#pragma unroll
            for (int i = 0; i < 2; i++)
                wmma::load_matrix_sync(a[i], &As[wm * 32 + i * 16][kk], GM_BK + 8);
#pragma unroll
            for (int j = 0; j < 4; j++)
                wmma::load_matrix_sync(b[j], &Ws[kk][wn * 64 + j * 16], HF + 8);
#pragma unroll
            for (int i = 0; i < 2; i++)
#pragma unroll
                for (int j = 0; j < 4; j++)
                    wmma::mma_sync(c[i][j], a[i], b[j], c[i][j]);
        }
        __syncthreads();
    }

    // store (g_h padded to N_PAD rows — unconditional full-tile stores are safe)
#pragma unroll
    for (int i = 0; i < 2; i++)
#pragma unroll
        for (int j = 0; j < 4; j++)
            wmma::store_matrix_sync(
                &g_h[(size_t)(m0 + wm * 32 + i * 16) * HF + wn * 64 + j * 16],
                c[i][j], HF, wmma::mem_row_major);
}

// ---------------------------------------------------------------------------
// h -> fp16 copy for fused gather (L2-hot right after GEMM)
// ---------------------------------------------------------------------------
__global__ void h2half_kernel() {
    int i = blockIdx.x * blockDim.x + threadIdx.x;
    int stride = gridDim.x * blockDim.x;
    const int n4 = (N_NODES * HF) / 4;
    for (int j = i; j < n4; j += stride) {
        float4 v = ((const float4*)g_h)[j];
        ((__half2*)g_hh)[j * 2]     = __floats2half2_rn(v.x, v.y);
        ((__half2*)g_hh)[j * 2 + 1] = __floats2half2_rn(v.z, v.w);
    }
}

// ---------------------------------------------------------------------------
// K2: q[n,h,k] = (1/sqrt(32)) * sum_f h[n,h*32+f] * W_edge[k, h*32+f]
// Computed fp32 (from fp32 h), stored fp16.
// ---------------------------------------------------------------------------
__global__ __launch_bounds__(256) void make_q_kernel(const float* __restrict__ We) {
    __shared__ float WeT[HF * EDGE_FEATS];   // WeT[c*64 + k] = We[k*128 + c]
    __shared__ float hs[4][HF];

    const int tid = threadIdx.x;
    for (int i = tid; i < EDGE_FEATS * HF; i += 256) {
        int k = i >> 7, c = i & 127;
        WeT[c * EDGE_FEATS + k] = We[i];
    }

    const int hh = tid >> 6;
    const int k  = tid & 63;
    const int node0 = blockIdx.x * 16;
    const float scale = 0.17677669529663687f;   // 1/sqrt(32)

    for (int g = 0; g < 4; g++) {
        __syncthreads();
        for (int i = tid; i < 4 * HF; i += 256) {
            int ni = i >> 7, c = i & 127;
            int n = node0 + g * 4 + ni;
            hs[ni][c] = (n < N_NODES) ? g_h[n * HF + c] : 0.0f;
        }
        __syncthreads();

        float acc[4] = {0.f, 0.f, 0.f, 0.f};
#pragma unroll
        for (int f = 0; f < OUT_FEATS; f++) {
            float w = WeT[(hh * OUT_FEATS + f) * EDGE_FEATS + k];
#pragma unroll
            for (int ni = 0; ni < 4; ni++) acc[ni] += hs[ni][hh * OUT_FEATS + f] * w;
        }
#pragma unroll
        for (int ni = 0; ni < 4; ni++) {
            int n = node0 + g * 4 + ni;
            if (n < N_NODES)
                g_qh[(n * NUM_HEADS + hh) * EDGE_FEATS + k] = __float2half_rn(acc[ni] * scale);
        }
    }
}

// ---------------------------------------------------------------------------
// CSR build: histogram -> scan (3 kernels) -> scatter (eid + psrc)
// ---------------------------------------------------------------------------
__global__ void hist_kernel(const int* __restrict__ dst) {
    int e = blockIdx.x * blockDim.x + threadIdx.x;
    if (e < N_EDGES) atomicAdd(&g_cnt[dst[e]], 1);
}

__global__ __launch_bounds__(SCAN_BLK) void scan1_kernel() {
    __shared__ int sm[SCAN_BLK];
    int t = threadIdx.x;
    int i = blockIdx.x * SCAN_BLK + t;
    sm[t] = (i < N_NODES) ? g_cnt[i] : 0;
    __syncthreads();
    for (int off = SCAN_BLK / 2; off > 0; off >>= 1) {
        if (t < off) sm[t] += sm[t + off];
        __syncthreads();
    }
    if (t == 0) g_part[blockIdx.x] = sm[0];
}

__global__ __launch_bounds__(128) void scan2_kernel() {
    __shared__ int sm[2][128];
    int t = threadIdx.x;
    int v = (t < NB_SCAN) ? g_part[t] : 0;
    int pi = 0;
    sm[0][t] = v;
    __syncthreads();
#pragma unroll
    for (int off = 1; off < 128; off <<= 1) {
        int add = (t >= off) ? sm[pi][t - off] : 0;
        sm[pi ^ 1][t] = sm[pi][t] + add;
        pi ^= 1;
        __syncthreads();
    }
    if (t < NB_SCAN) g_partx[t] = sm[pi][t] - v;   // exclusive
}

__global__ __launch_bounds__(SCAN_BLK) void scan3_kernel() {
    __shared__ int sm[2][SCAN_BLK];
    int t = threadIdx.x;
    int i = blockIdx.x * SCAN_BLK + t;
    int v = (i < N_NODES) ? g_cnt[i] : 0;
    int pi = 0;
    sm[0][t] = v;
    __syncthreads();
#pragma unroll
    for (int off = 1; off < SCAN_BLK; off <<= 1) {
        int add = (t >= off) ? sm[pi][t - off] : 0;
        sm[pi ^ 1][t] = sm[pi][t] + add;
        pi ^= 1;
        __syncthreads();
    }
    if (i < N_NODES) {
        int excl = g_partx[blockIdx.x] + sm[pi][t] - v;
        g_off[i] = excl;
        g_cur[i] = excl;
    }
    if (blockIdx.x == 0 && t == 0) g_off[N_NODES] = N_EDGES;
}

__global__ void scatter_kernel(const int* __restrict__ src, const int* __restrict__ dst) {
    int e = blockIdx.x * blockDim.x + threadIdx.x;
    if (e < N_EDGES) {
        int pos = atomicAdd(&g_cur[dst[e]], 1);
        g_eid[pos]  = e;
        g_psrc[pos] = src[e];
    }
}

// ---------------------------------------------------------------------------
// Fused: warp per dst node, NO max subtraction (softmax shift-invariant,
// scores O(1)). lane l: head h=l>>3, k-chunk k0=(l&7)*8.
// ---------------------------------------------------------------------------
__global__ __launch_bounds__(256) void fused_kernel(
    const float* __restrict__ ef, float* __restrict__ out) {
    const int d = (blockIdx.x * 256 + threadIdx.x) >> 5;
    if (d >= N_NODES) return;
    const int lane = threadIdx.x & 31;
    const int h  = lane >> 3;
    const int k0 = (lane & 7) * 8;

    const int beg = __ldg(&g_off[d]);
    const int end = __ldg(&g_off[d + 1]);

    float den = 0.0f;
    float4 acc = make_float4(0.f, 0.f, 0.f, 0.f);

    int eid = 0, s = 0;
    if (beg < end) {
        eid = __ldg(&g_eid[beg]);
        s   = __ldg(&g_psrc[beg]);
    }

    for (int j = beg; j < end; j++) {
        const int eid_c = eid;
        const int s_c = s;
        if (j + 1 < end) {
            eid = __ldg(&g_eid[j + 1]);
            s   = __ldg(&g_psrc[j + 1]);
        }

        const float4 ef0 = *(const float4*)(ef + (size_t)eid_c * EDGE_FEATS + k0);
        const float4 ef1 = *(const float4*)(ef + (size_t)eid_c * EDGE_FEATS + k0 + 4);

        const uint4 qv = *(const uint4*)(g_qh + (size_t)s_c * QCOLS + h * EDGE_FEATS + k0);
        const float2 q0 = __half22float2(*(const __half2*)&qv.x);
        const float2 q1 = __half22float2(*(((const __half2*)&qv.x) + 1));
        const float2 q2 = __half22float2(*(const __half2*)&qv.z);
        const float2 q3 = __half22float2(*(((const __half2*)&qv.z) + 1));

        float p = ef0.x * q0.x + ef0.y * q0.y + ef0.z * q1.x + ef0.w * q1.y
                + ef1.x * q2.x + ef1.y * q2.y + ef1.z * q3.x + ef1.w * q3.y;
        p += __shfl_xor_sync(0xffffffffu, p, 1);
        p += __shfl_xor_sync(0xffffffffu, p, 2);
        p += __shfl_xor_sync(0xffffffffu, p, 4);

        const float sc = (p > 0.0f) ? p : 0.01f * p;       // leaky relu
        const float w  = __expf(sc);

        const uint2 hvu = *(const uint2*)(g_hh + (size_t)s_c * HF + lane * 4);
        const float2 h01 = __half22float2(*(const __half2*)&hvu.x);
        const float2 h23 = __half22float2(*(const __half2*)&hvu.y);

        den   += w;
        acc.x += w * h01.x;
        acc.y += w * h01.y;
        acc.z += w * h23.x;
        acc.w += w * h23.y;
    }

    const float inv = (den > 0.0f) ? __frcp_rn(den) : 0.0f;
    float4 o = make_float4(acc.x * inv, acc.y * inv, acc.z * inv, acc.w * inv);
    *(float4*)(out + (size_t)d * HF + lane * 4) = o;
}

// ---------------------------------------------------------------------------
extern "C" void kernel_launch(void* const* d_in, const int* in_sizes, int n_in,
                              void* d_out, int out_size) {
    const float* node_feat = (const float*)d_in[0];
    const float* edge_feat = (const float*)d_in[1];
    const int*   src       = (const int*)d_in[2];
    const int*   dst       = (const int*)d_in[3];
    const float* W_node    = (const float*)d_in[4];
    const float* W_edge    = (const float*)d_in[5];
    float* out = (float*)d_out;

    zero_cnt_kernel<<<(N_NODES + 255) / 256, 256>>>();
    gemm_wmma_kernel<<<(N_NODES + GM_BM - 1) / GM_BM, 256>>>(node_feat, W_node);  // 391 blocks
    h2half_kernel<<<2048, 256>>>();
    make_q_kernel<<<(N_NODES + 15) / 16, 256>>>(W_edge);
    hist_kernel<<<(N_EDGES + 255) / 256, 256>>>(dst);
    scan1_kernel<<<NB_SCAN, SCAN_BLK>>>();
    scan2_kernel<<<1, 128>>>();
    scan3_kernel<<<NB_SCAN, SCAN_BLK>>>();
    scatter_kernel<<<(N_EDGES + 255) / 256, 256>>>(src, dst);
    fused_kernel<<<(N_NODES * 32 + 255) / 256, 256>>>(edge_feat, out);
}

// round 8
// speedup vs baseline: 1.7998x; 1.4371x over previous
#include <cuda_runtime.h>
#include <cuda_bf16.h>
#include <cuda_fp16.h>
#include <mma.h>
#include <math_constants.h>

using namespace nvcuda;

// Problem constants
#define N_NODES   50000
#define N_EDGES   800000
#define IN_FEATS  256
#define EDGE_FEATS 64
#define NUM_HEADS 4
#define OUT_FEATS 32
#define HF        128           // NUM_HEADS*OUT_FEATS
#define QCOLS     256           // NUM_HEADS*EDGE_FEATS
#define NCAT      384           // HF + QCOLS

#define SCAN_BLK  512
#define NB_SCAN   ((N_NODES + SCAN_BLK - 1) / SCAN_BLK)   // 98

#define GM_BM 128
#define GM_BK 32

// Scratch (static device globals; no allocation allowed)
__device__ __half g_wcat[IN_FEATS * NCAT];     // [W_node | W_node@Wbig*scale] fp16
__device__ __half g_hh[N_NODES * HF];          // projected node feats fp16
__device__ __half g_qh[N_NODES * QCOLS];       // q[n,h,k] fp16 (scale baked in)
__device__ int    g_cnt[N_NODES];
__device__ int    g_off[N_NODES + 1];
__device__ int    g_cur[N_NODES];
__device__ int    g_eid[N_EDGES];
__device__ int    g_psrc[N_EDGES];
__device__ int    g_part[NB_SCAN];
__device__ int    g_partx[NB_SCAN];

// ---------------------------------------------------------------------------
__global__ void zero_cnt_kernel() {
    int i = blockIdx.x * blockDim.x + threadIdx.x;
    if (i < N_NODES) g_cnt[i] = 0;
}

// ---------------------------------------------------------------------------
// Wcat precompute: block = input channel c_in (256 blocks), thread = out col j.
//   j <  128: Wcat = W_node[c_in, j]
//   j >= 128: jj=j-128, h=jj>>6, k=jj&63:
//             Wcat = (1/sqrt32) * sum_f W_node[c_in, h*32+f] * We[k, h*32+f]
// ---------------------------------------------------------------------------
__global__ __launch_bounds__(NCAT) void wcat_kernel(
    const float* __restrict__ Wn, const float* __restrict__ We) {
    __shared__ float We_s[EDGE_FEATS * HF];   // 32KB
    __shared__ float wn_row[HF];

    const int c_in = blockIdx.x;
    const int j = threadIdx.x;

    for (int i = j; i < EDGE_FEATS * HF; i += NCAT) We_s[i] = We[i];
    if (j < HF) wn_row[j] = Wn[(size_t)c_in * HF + j];
    __syncthreads();

    float out;
    if (j < HF) {
        out = wn_row[j];
    } else {
        const int jj = j - HF;
        const int h = jj >> 6;
        const int k = jj & 63;
        float acc = 0.0f;
#pragma unroll
        for (int f = 0; f < OUT_FEATS; f++)
            acc += wn_row[h * OUT_FEATS + f] * We_s[k * HF + h * OUT_FEATS + f];
        out = acc * 0.17677669529663687f;   // 1/sqrt(32)
    }
    g_wcat[(size_t)c_in * NCAT + j] = __float2half_rn(out);
}

// ---------------------------------------------------------------------------
// Single fused GEMM: [h | q] = A[50000,256] @ Wcat[256,384], wmma fp16/fp32.
// grid (m_tiles=391, n_tiles=3); block 256 thr = 8 warps, warp tile 32x64.
// Epilogue converts fp32 accum -> fp16 and writes g_hh (cols<128) or g_qh.
// ---------------------------------------------------------------------------
__global__ __launch_bounds__(256) void gemm_cat_kernel(const float* __restrict__ A) {
    __shared__ __half As[GM_BM][GM_BK + 8];   // 128x40 halves
    __shared__ __half Ws[GM_BK][128 + 8];     // 32x136 halves
    __shared__ float  patch[8][16 * 16];      // per-warp fragment staging (8KB)

    const int tid  = threadIdx.x;
    const int warp = tid >> 5;
    const int lane = tid & 31;
    const int wm   = warp >> 1;     // 0..3
    const int wn   = warp & 1;      // 0..1
    const int m0   = blockIdx.x * GM_BM;
    const int nbase = blockIdx.y * 128;

    wmma::fragment<wmma::accumulator, 16, 16, 16, float> c[2][4];
#pragma unroll
    for (int i = 0; i < 2; i++)
#pragma unroll
        for (int j = 0; j < 4; j++) wmma::fill_fragment(c[i][j], 0.0f);

    for (int k0 = 0; k0 < IN_FEATS; k0 += GM_BK) {
        // A tile: 128x32 fp32 -> fp16
#pragma unroll
        for (int i = 0; i < 4; i++) {
            int idx = tid + i * 256;        // 0..1023
            int row = idx >> 3;
            int col = (idx & 7) * 4;
            float4 v = make_float4(0.f, 0.f, 0.f, 0.f);
            int gr = m0 + row;
            if (gr < N_NODES) v = *(const float4*)&A[(size_t)gr * IN_FEATS + k0 + col];
            As[row][col + 0] = __float2half_rn(v.x);
            As[row][col + 1] = __float2half_rn(v.y);
            As[row][col + 2] = __float2half_rn(v.z);
            As[row][col + 3] = __float2half_rn(v.w);
        }
        // W tile: 32x128 halves from g_wcat (already fp16): 512 uint4, 2/thread
#pragma unroll
        for (int i = 0; i < 2; i++) {
            int idx = tid + i * 256;        // 0..511
            int row = idx >> 4;             // 16 uint4 per row
            int col = (idx & 15) * 8;
            *(uint4*)&Ws[row][col] =
                *(const uint4*)&g_wcat[(size_t)(k0 + row) * NCAT + nbase + col];
        }
        __syncthreads();

#pragma unroll
        for (int kk = 0; kk < GM_BK; kk += 16) {
            wmma::fragment<wmma::matrix_a, 16, 16, 16, __half, wmma::row_major> a[2];
            wmma::fragment<wmma::matrix_b, 16, 16, 16, __half, wmma::row_major> b[4];
#pragma unroll
            for (int i = 0; i < 2; i++)
                wmma::load_matrix_sync(a[i], &As[wm * 32 + i * 16][kk], GM_BK + 8);
#pragma unroll
            for (int j = 0; j < 4; j++)
                wmma::load_matrix_sync(b[j], &Ws[kk][wn * 64 + j * 16], 128 + 8);
#pragma unroll
            for (int i = 0; i < 2; i++)
#pragma unroll
                for (int j = 0; j < 4; j++)
                    wmma::mma_sync(c[i][j], a[i], b[j], c[i][j]);
        }
        __syncthreads();
    }

    // Epilogue: fragment -> smem patch -> fp16 global (g_hh or g_qh).
    // lane covers row lane>>1, cols (lane&1)*8 .. +8 of each 16x16 fragment.
    const int prow = lane >> 1;
    const int pcol = (lane & 1) * 8;
#pragma unroll
    for (int i = 0; i < 2; i++) {
#pragma unroll
        for (int j = 0; j < 4; j++) {
            wmma::store_matrix_sync(patch[warp], c[i][j], 16, wmma::mem_row_major);
            __syncwarp();
            const int n = m0 + wm * 32 + i * 16 + prow;
            if (n < N_NODES) {
                const float* pr = patch[warp] + prow * 16 + pcol;
                union { uint4 u; __half2 h2[4]; } pack;
                pack.h2[0] = __floats2half2_rn(pr[0], pr[1]);
                pack.h2[1] = __floats2half2_rn(pr[2], pr[3]);
                pack.h2[2] = __floats2half2_rn(pr[4], pr[5]);
                pack.h2[3] = __floats2half2_rn(pr[6], pr[7]);
                const int C = nbase + wn * 64 + j * 16 + pcol;   // global col 0..383
                if (C < HF) {
                    *(uint4*)&g_hh[(size_t)n * HF + C] = pack.u;
                } else {
                    *(uint4*)&g_qh[(size_t)n * QCOLS + (C - HF)] = pack.u;
                }
            }
            __syncwarp();
        }
    }
}

// ---------------------------------------------------------------------------
// CSR build: histogram -> scan (3 kernels) -> scatter (eid + psrc)
// ---------------------------------------------------------------------------
__global__ void hist_kernel(const int* __restrict__ dst) {
    int e = blockIdx.x * blockDim.x + threadIdx.x;
    if (e < N_EDGES) atomicAdd(&g_cnt[dst[e]], 1);
}

__global__ __launch_bounds__(SCAN_BLK) void scan1_kernel() {
    __shared__ int sm[SCAN_BLK];
    int t = threadIdx.x;
    int i = blockIdx.x * SCAN_BLK + t;
    sm[t] = (i < N_NODES) ? g_cnt[i] : 0;
    __syncthreads();
    for (int off = SCAN_BLK / 2; off > 0; off >>= 1) {
        if (t < off) sm[t] += sm[t + off];
        __syncthreads();
    }
    if (t == 0) g_part[blockIdx.x] = sm[0];
}

__global__ __launch_bounds__(128) void scan2_kernel() {
    __shared__ int sm[2][128];
    int t = threadIdx.x;
    int v = (t < NB_SCAN) ? g_part[t] : 0;
    int pi = 0;
    sm[0][t] = v;
    __syncthreads();
#pragma unroll
    for (int off = 1; off < 128; off <<= 1) {
        int add = (t >= off) ? sm[pi][t - off] : 0;
        sm[pi ^ 1][t] = sm[pi][t] + add;
        pi ^= 1;
        __syncthreads();
    }
    if (t < NB_SCAN) g_partx[t] = sm[pi][t] - v;   // exclusive
}

__global__ __launch_bounds__(SCAN_BLK) void scan3_kernel() {
    __shared__ int sm[2][SCAN_BLK];
    int t = threadIdx.x;
    int i = blockIdx.x * SCAN_BLK + t;
    int v = (i < N_NODES) ? g_cnt[i] : 0;
    int pi = 0;
    sm[0][t] = v;
    __syncthreads();
#pragma unroll
    for (int off = 1; off < SCAN_BLK; off <<= 1) {
        int add = (t >= off) ? sm[pi][t - off] : 0;
        sm[pi ^ 1][t] = sm[pi][t] + add;
        pi ^= 1;
        __syncthreads();
    }
    if (i < N_NODES) {
        int excl = g_partx[blockIdx.x] + sm[pi][t] - v;
        g_off[i] = excl;
        g_cur[i] = excl;
    }
    if (blockIdx.x == 0 && t == 0) g_off[N_NODES] = N_EDGES;
}

__global__ void scatter_kernel(const int* __restrict__ src, const int* __restrict__ dst) {
    int e = blockIdx.x * blockDim.x + threadIdx.x;
    if (e < N_EDGES) {
        int pos = atomicAdd(&g_cur[dst[e]], 1);
        g_eid[pos]  = e;
        g_psrc[pos] = src[e];
    }
}

// ---------------------------------------------------------------------------
// Fused: warp per dst node, NO max subtraction (softmax shift-invariant,
// scores O(1)). lane l: head h=l>>3, k-chunk k0=(l&7)*8.
// ---------------------------------------------------------------------------
__global__ __launch_bounds__(256) void fused_kernel(
    const float* __restrict__ ef, float* __restrict__ out) {
    const int d = (blockIdx.x * 256 + threadIdx.x) >> 5;
    if (d >= N_NODES) return;
    const int lane = threadIdx.x & 31;
    const int h  = lane >> 3;
    const int k0 = (lane & 7) * 8;

    const int beg = __ldg(&g_off[d]);
    const int end = __ldg(&g_off[d + 1]);

    float den = 0.0f;
    float4 acc = make_float4(0.f, 0.f, 0.f, 0.f);

    int eid = 0, s = 0;
    if (beg < end) {
        eid = __ldg(&g_eid[beg]);
        s   = __ldg(&g_psrc[beg]);
    }

    for (int j = beg; j < end; j++) {
        const int eid_c = eid;
        const int s_c = s;
        if (j + 1 < end) {
            eid = __ldg(&g_eid[j + 1]);
            s   = __ldg(&g_psrc[j + 1]);
        }

        const float4 ef0 = *(const float4*)(ef + (size_t)eid_c * EDGE_FEATS + k0);
        const float4 ef1 = *(const float4*)(ef + (size_t)eid_c * EDGE_FEATS + k0 + 4);

        const uint4 qv = *(const uint4*)(g_qh + (size_t)s_c * QCOLS + h * EDGE_FEATS + k0);
        const float2 q0 = __half22float2(*(const __half2*)&qv.x);
        const float2 q1 = __half22float2(*(((const __half2*)&qv.x) + 1));
        const float2 q2 = __half22float2(*(const __half2*)&qv.z);
        const float2 q3 = __half22float2(*(((const __half2*)&qv.z) + 1));

        float p = ef0.x * q0.x + ef0.y * q0.y + ef0.z * q1.x + ef0.w * q1.y
                + ef1.x * q2.x + ef1.y * q2.y + ef1.z * q3.x + ef1.w * q3.y;
        p += __shfl_xor_sync(0xffffffffu, p, 1);
        p += __shfl_xor_sync(0xffffffffu, p, 2);
        p += __shfl_xor_sync(0xffffffffu, p, 4);

        const float sc = (p > 0.0f) ? p : 0.01f * p;       // leaky relu
        const float w  = __expf(sc);

        const uint2 hvu = *(const uint2*)(g_hh + (size_t)s_c * HF + lane * 4);
        const float2 h01 = __half22float2(*(const __half2*)&hvu.x);
        const float2 h23 = __half22float2(*(const __half2*)&hvu.y);

        den   += w;
        acc.x += w * h01.x;
        acc.y += w * h01.y;
        acc.z += w * h23.x;
        acc.w += w * h23.y;
    }

    const float inv = (den > 0.0f) ? __frcp_rn(den) : 0.0f;
    float4 o = make_float4(acc.x * inv, acc.y * inv, acc.z * inv, acc.w * inv);
    *(float4*)(out + (size_t)d * HF + lane * 4) = o;
}

// ---------------------------------------------------------------------------
extern "C" void kernel_launch(void* const* d_in, const int* in_sizes, int n_in,
                              void* d_out, int out_size) {
    const float* node_feat = (const float*)d_in[0];
    const float* edge_feat = (const float*)d_in[1];
    const int*   src       = (const int*)d_in[2];
    const int*   dst       = (const int*)d_in[3];
    const float* W_node    = (const float*)d_in[4];
    const float* W_edge    = (const float*)d_in[5];
    float* out = (float*)d_out;

    zero_cnt_kernel<<<(N_NODES + 255) / 256, 256>>>();
    wcat_kernel<<<IN_FEATS, NCAT>>>(W_node, W_edge);
    dim3 ggrid((N_NODES + GM_BM - 1) / GM_BM, 3);
    gemm_cat_kernel<<<ggrid, 256>>>(node_feat);
    hist_kernel<<<(N_EDGES + 255) / 256, 256>>>(dst);
    scan1_kernel<<<NB_SCAN, SCAN_BLK>>>();
    scan2_kernel<<<1, 128>>>();
    scan3_kernel<<<NB_SCAN, SCAN_BLK>>>();
    scatter_kernel<<<(N_EDGES + 255) / 256, 256>>>(src, dst);
    fused_kernel<<<(N_NODES * 32 + 255) / 256, 256>>>(edge_feat, out);
}

// round 9
// speedup vs baseline: 1.8920x; 1.0512x over previous
#include <cuda_runtime.h>
#include <cuda_bf16.h>
#include <cuda_fp16.h>
#include <mma.h>
#include <math_constants.h>

using namespace nvcuda;

// Problem constants
#define N_NODES   50000
#define N_EDGES   800000
#define IN_FEATS  256
#define EDGE_FEATS 64
#define NUM_HEADS 4
#define OUT_FEATS 32
#define HF        128           // NUM_HEADS*OUT_FEATS
#define QCOLS     256           // NUM_HEADS*EDGE_FEATS
#define NCAT      384           // HF + QCOLS

#define SCAN_BLK  512
#define NB_SCAN   ((N_NODES + SCAN_BLK - 1) / SCAN_BLK)   // 98

#define GM_BM 128
#define GM_BK 32

// Scratch (static device globals; no allocation allowed)
__device__ __half g_wcat[IN_FEATS * NCAT];     // [W_node | W_node@Wbig*scale] fp16
__device__ __half g_hh[N_NODES * HF];          // projected node feats fp16
__device__ __half g_qh[N_NODES * QCOLS];       // q[n,h,k] fp16 (scale baked in)
__device__ int    g_cnt[N_NODES];
__device__ int    g_off[N_NODES + 1];
__device__ int    g_cur[N_NODES];
__device__ int2   g_es[N_EDGES];               // (eid, src) grouped by dst
__device__ int    g_part[NB_SCAN];
__device__ int    g_partx[NB_SCAN];

// ---------------------------------------------------------------------------
// Wcat precompute (also zeroes g_cnt: 256 blocks x 384 thr = 98304 >= 50000).
//   j <  128: Wcat = W_node[c_in, j]
//   j >= 128: jj=j-128, h=jj>>6, k=jj&63:
//             Wcat = (1/sqrt32) * sum_f W_node[c_in, h*32+f] * We[k, h*32+f]
// ---------------------------------------------------------------------------
__global__ __launch_bounds__(NCAT) void wcat_kernel(
    const float* __restrict__ Wn, const float* __restrict__ We) {
    __shared__ float We_s[EDGE_FEATS * HF];   // 32KB
    __shared__ float wn_row[HF];

    const int c_in = blockIdx.x;
    const int j = threadIdx.x;

    // fold-in: zero in-degree histogram
    const int zi = blockIdx.x * NCAT + j;
    if (zi < N_NODES) g_cnt[zi] = 0;

    for (int i = j; i < EDGE_FEATS * HF; i += NCAT) We_s[i] = We[i];
    if (j < HF) wn_row[j] = Wn[(size_t)c_in * HF + j];
    __syncthreads();

    float out;
    if (j < HF) {
        out = wn_row[j];
    } else {
        const int jj = j - HF;
        const int h = jj >> 6;
        const int k = jj & 63;
        float acc = 0.0f;
#pragma unroll
        for (int f = 0; f < OUT_FEATS; f++)
            acc += wn_row[h * OUT_FEATS + f] * We_s[k * HF + h * OUT_FEATS + f];
        out = acc * 0.17677669529663687f;   // 1/sqrt(32)
    }
    g_wcat[(size_t)c_in * NCAT + j] = __float2half_rn(out);
}

// ---------------------------------------------------------------------------
// Single fused GEMM: [h | q] = A[50000,256] @ Wcat[256,384], wmma fp16/fp32.
// grid (n_tiles=3, m_tiles=391): the 3 n-tiles of one m-tile are adjacent in
// launch order -> A slab L2 reuse (A DRAM read ~1x instead of 3x).
// ---------------------------------------------------------------------------
__global__ __launch_bounds__(256) void gemm_cat_kernel(const float* __restrict__ A) {
    __shared__ __half As[GM_BM][GM_BK + 8];   // 128x40 halves
    __shared__ __half Ws[GM_BK][128 + 8];     // 32x136 halves
    __shared__ float  patch[8][16 * 16];      // per-warp fragment staging (8KB)

    const int tid  = threadIdx.x;
    const int warp = tid >> 5;
    const int lane = tid & 31;
    const int wm   = warp >> 1;     // 0..3
    const int wn   = warp & 1;      // 0..1
    const int m0   = blockIdx.y * GM_BM;
    const int nbase = blockIdx.x * 128;

    wmma::fragment<wmma::accumulator, 16, 16, 16, float> c[2][4];
#pragma unroll
    for (int i = 0; i < 2; i++)
#pragma unroll
        for (int j = 0; j < 4; j++) wmma::fill_fragment(c[i][j], 0.0f);

    for (int k0 = 0; k0 < IN_FEATS; k0 += GM_BK) {
        // A tile: 128x32 fp32 -> fp16
#pragma unroll
        for (int i = 0; i < 4; i++) {
            int idx = tid + i * 256;        // 0..1023
            int row = idx >> 3;
            int col = (idx & 7) * 4;
            float4 v = make_float4(0.f, 0.f, 0.f, 0.f);
            int gr = m0 + row;
            if (gr < N_NODES) v = *(const float4*)&A[(size_t)gr * IN_FEATS + k0 + col];
            As[row][col + 0] = __float2half_rn(v.x);
            As[row][col + 1] = __float2half_rn(v.y);
            As[row][col + 2] = __float2half_rn(v.z);
            As[row][col + 3] = __float2half_rn(v.w);
        }
        // W tile: 32x128 halves from g_wcat: 512 uint4, 2/thread
#pragma unroll
        for (int i = 0; i < 2; i++) {
            int idx = tid + i * 256;        // 0..511
            int row = idx >> 4;             // 16 uint4 per row
            int col = (idx & 15) * 8;
            *(uint4*)&Ws[row][col] =
                *(const uint4*)&g_wcat[(size_t)(k0 + row) * NCAT + nbase + col];
        }
        __syncthreads();

#pragma unroll
        for (int kk = 0; kk < GM_BK; kk += 16) {
            wmma::fragment<wmma::matrix_a, 16, 16, 16, __half, wmma::row_major> a[2];
            wmma::fragment<wmma::matrix_b, 16, 16, 16, __half, wmma::row_major> b[4];
#pragma unroll
            for (int i = 0; i < 2; i++)
                wmma::load_matrix_sync(a[i], &As[wm * 32 + i * 16][kk], GM_BK + 8);
#pragma unroll
            for (int j = 0; j < 4; j++)
                wmma::load_matrix_sync(b[j], &Ws[kk][wn * 64 + j * 16], 128 + 8);
#pragma unroll
            for (int i = 0; i < 2; i++)
#pragma unroll
                for (int j = 0; j < 4; j++)
                    wmma::mma_sync(c[i][j], a[i], b[j], c[i][j]);
        }
        __syncthreads();
    }

    // Epilogue: fragment -> smem patch -> fp16 global (g_hh or g_qh).
    const int prow = lane >> 1;
    const int pcol = (lane & 1) * 8;
#pragma unroll
    for (int i = 0; i < 2; i++) {
#pragma unroll
        for (int j = 0; j < 4; j++) {
            wmma::store_matrix_sync(patch[warp], c[i][j], 16, wmma::mem_row_major);
            __syncwarp();
            const int n = m0 + wm * 32 + i * 16 + prow;
            if (n < N_NODES) {
                const float* pr = patch[warp] + prow * 16 + pcol;
                union { uint4 u; __half2 h2[4]; } pack;
                pack.h2[0] = __floats2half2_rn(pr[0], pr[1]);
                pack.h2[1] = __floats2half2_rn(pr[2], pr[3]);
                pack.h2[2] = __floats2half2_rn(pr[4], pr[5]);
                pack.h2[3] = __floats2half2_rn(pr[6], pr[7]);
                const int C = nbase + wn * 64 + j * 16 + pcol;   // 0..383
                if (C < HF) {
                    *(uint4*)&g_hh[(size_t)n * HF + C] = pack.u;
                } else {
                    *(uint4*)&g_qh[(size_t)n * QCOLS + (C - HF)] = pack.u;
                }
            }
            __syncwarp();
        }
    }
}

// ---------------------------------------------------------------------------
// CSR build: histogram -> scan (3 kernels) -> scatter (packed int2)
// ---------------------------------------------------------------------------
__global__ void hist_kernel(const int* __restrict__ dst) {
    int e = blockIdx.x * blockDim.x + threadIdx.x;
    if (e < N_EDGES) atomicAdd(&g_cnt[dst[e]], 1);
}

__global__ __launch_bounds__(SCAN_BLK) void scan1_kernel() {
    __shared__ int sm[SCAN_BLK];
    int t = threadIdx.x;
    int i = blockIdx.x * SCAN_BLK + t;
    sm[t] = (i < N_NODES) ? g_cnt[i] : 0;
    __syncthreads();
    for (int off = SCAN_BLK / 2; off > 0; off >>= 1) {
        if (t < off) sm[t] += sm[t + off];
        __syncthreads();
    }
    if (t == 0) g_part[blockIdx.x] = sm[0];
}

__global__ __launch_bounds__(128) void scan2_kernel() {
    __shared__ int sm[2][128];
    int t = threadIdx.x;
    int v = (t < NB_SCAN) ? g_part[t] : 0;
    int pi = 0;
    sm[0][t] = v;
    __syncthreads();
#pragma unroll
    for (int off = 1; off < 128; off <<= 1) {
        int add = (t >= off) ? sm[pi][t - off] : 0;
        sm[pi ^ 1][t] = sm[pi][t] + add;
        pi ^= 1;
        __syncthreads();
    }
    if (t < NB_SCAN) g_partx[t] = sm[pi][t] - v;   // exclusive
}

__global__ __launch_bounds__(SCAN_BLK) void scan3_kernel() {
    __shared__ int sm[2][SCAN_BLK];
    int t = threadIdx.x;
    int i = blockIdx.x * SCAN_BLK + t;
    int v = (i < N_NODES) ? g_cnt[i] : 0;
    int pi = 0;
    sm[0][t] = v;
    __syncthreads();
#pragma unroll
    for (int off = 1; off < SCAN_BLK; off <<= 1) {
        int add = (t >= off) ? sm[pi][t - off] : 0;
        sm[pi ^ 1][t] = sm[pi][t] + add;
        pi ^= 1;
        __syncthreads();
    }
    if (i < N_NODES) {
        int excl = g_partx[blockIdx.x] + sm[pi][t] - v;
        g_off[i] = excl;
        g_cur[i] = excl;
    }
    if (blockIdx.x == 0 && t == 0) g_off[N_NODES] = N_EDGES;
}

__global__ void scatter_kernel(const int* __restrict__ src, const int* __restrict__ dst) {
    int e = blockIdx.x * blockDim.x + threadIdx.x;
    if (e < N_EDGES) {
        int pos = atomicAdd(&g_cur[dst[e]], 1);
        g_es[pos] = make_int2(e, src[e]);
    }
}

// ---------------------------------------------------------------------------
// Fused: warp per dst node, NO max subtraction (softmax shift-invariant,
// scores O(1)). lane l: head h=l>>3, k-chunk k0=(l&7)*8.
// ---------------------------------------------------------------------------
__global__ __launch_bounds__(256) void fused_kernel(
    const float* __restrict__ ef, float* __restrict__ out) {
    const int d = (blockIdx.x * 256 + threadIdx.x) >> 5;
    if (d >= N_NODES) return;
    const int lane = threadIdx.x & 31;
    const int h  = lane >> 3;
    const int k0 = (lane & 7) * 8;

    const int beg = __ldg(&g_off[d]);
    const int end = __ldg(&g_off[d + 1]);

    float den = 0.0f;
    float4 acc = make_float4(0.f, 0.f, 0.f, 0.f);

    if (beg < end) {
        int2 es = __ldg(&g_es[beg]);   // (eid, src) one LDG.64
        const int last = end - 1;

#pragma unroll 2
        for (int j = beg; j < end; j++) {
            const int eid_c = es.x;
            const int s_c   = es.y;
            const int jn = (j < last) ? j + 1 : last;   // clamped, branch-free
            es = __ldg(&g_es[jn]);

            const float4 ef0 = *(const float4*)(ef + (size_t)eid_c * EDGE_FEATS + k0);
            const float4 ef1 = *(const float4*)(ef + (size_t)eid_c * EDGE_FEATS + k0 + 4);

            const uint4 qv = *(const uint4*)(g_qh + (size_t)s_c * QCOLS + h * EDGE_FEATS + k0);
            const float2 q0 = __half22float2(*(const __half2*)&qv.x);
            const float2 q1 = __half22float2(*(((const __half2*)&qv.x) + 1));
            const float2 q2 = __half22float2(*(const __half2*)&qv.z);
            const float2 q3 = __half22float2(*(((const __half2*)&qv.z) + 1));

            float p = ef0.x * q0.x + ef0.y * q0.y + ef0.z * q1.x + ef0.w * q1.y
                    + ef1.x * q2.x + ef1.y * q2.y + ef1.z * q3.x + ef1.w * q3.y;
            p += __shfl_xor_sync(0xffffffffu, p, 1);
            p += __shfl_xor_sync(0xffffffffu, p, 2);
            p += __shfl_xor_sync(0xffffffffu, p, 4);

            const float sc = (p > 0.0f) ? p : 0.01f * p;   // leaky relu
            const float w  = __expf(sc);

            const uint2 hvu = *(const uint2*)(g_hh + (size_t)s_c * HF + lane * 4);
            const float2 h01 = __half22float2(*(const __half2*)&hvu.x);
            const float2 h23 = __half22float2(*(const __half2*)&hvu.y);

            den   += w;
            acc.x += w * h01.x;
            acc.y += w * h01.y;
            acc.z += w * h23.x;
            acc.w += w * h23.y;
        }
    }

    const float inv = (den > 0.0f) ? __frcp_rn(den) : 0.0f;
    float4 o = make_float4(acc.x * inv, acc.y * inv, acc.z * inv, acc.w * inv);
    *(float4*)(out + (size_t)d * HF + lane * 4) = o;
}

// ---------------------------------------------------------------------------
extern "C" void kernel_launch(void* const* d_in, const int* in_sizes, int n_in,
                              void* d_out, int out_size) {
    const float* node_feat = (const float*)d_in[0];
    const float* edge_feat = (const float*)d_in[1];
    const int*   src       = (const int*)d_in[2];
    const int*   dst       = (const int*)d_in[3];
    const float* W_node    = (const float*)d_in[4];
    const float* W_edge    = (const float*)d_in[5];
    float* out = (float*)d_out;

    wcat_kernel<<<IN_FEATS, NCAT>>>(W_node, W_edge);   // also zeroes g_cnt
    dim3 ggrid(3, (N_NODES + GM_BM - 1) / GM_BM);
    gemm_cat_kernel<<<ggrid, 256>>>(node_feat);
    hist_kernel<<<(N_EDGES + 255) / 256, 256>>>(dst);
    scan1_kernel<<<NB_SCAN, SCAN_BLK>>>();
    scan2_kernel<<<1, 128>>>();
    scan3_kernel<<<NB_SCAN, SCAN_BLK>>>();
    scatter_kernel<<<(N_EDGES + 255) / 256, 256>>>(src, dst);
    fused_kernel<<<(N_NODES * 32 + 255) / 256, 256>>>(edge_feat, out);
}